// round 1
// baseline (speedup 1.0000x reference)
#include <cuda_runtime.h>
#include <cuda_bf16.h>

// Problem constants
#define T_TOTAL 4096
#define LAYERS  8
#define HIDDEN  1024
#define G4      4096   // 4*HIDDEN gate rows
#define LETTERS 100
#define NCTA    128
#define TPB     256
#define NCELLS  (T_TOTAL * LAYERS)   // 32768

// Scratch: precomputed input projections  Gin[t][l][row] = W_ih[l]@x_t + b_ih + b_hh
__device__ float g_gin[(size_t)T_TOTAL * LAYERS * G4];   // 512 MB
__device__ __align__(16) float g_h[2][HIDDEN];           // ping-pong hidden state
__device__ __align__(16) float g_c[HIDDEN];              // final cell state
__device__ unsigned g_bar;                               // grid barrier counter

__device__ __forceinline__ unsigned ld_acquire_u32(unsigned* p) {
    unsigned v;
    asm volatile("ld.acquire.gpu.global.u32 %0, [%1];" : "=r"(v) : "l"(p) : "memory");
    return v;
}

__device__ __forceinline__ float sigmoidf_(float x) {
    return 1.0f / (1.0f + expf(-x));
}

// ---------------------------------------------------------------------------
// Phase 1: precompute input projections; also reset recurrent state + barrier
// grid (32 rtiles, 8 layers, 256 ttiles), block 128
// ---------------------------------------------------------------------------
__global__ void precompute_kernel(const float* __restrict__ website,
                                  const float* __restrict__ payload,
                                  const float* __restrict__ W_ih,
                                  const float* __restrict__ b_ih,
                                  const float* __restrict__ b_hh) {
    __shared__ float Xsm[16 * LETTERS];
    const int rt = blockIdx.x;
    const int l  = blockIdx.y;
    const int t0 = blockIdx.z * 16;

    // Load 16 timesteps of x (concat(website, payload)) into smem
    for (int idx = threadIdx.x; idx < 16 * LETTERS; idx += 128) {
        int tt = idx / LETTERS, k = idx % LETTERS;
        int t = t0 + tt;
        Xsm[idx] = (t < 2048) ? website[t * LETTERS + k]
                              : payload[(t - 2048) * LETTERS + k];
    }
    __syncthreads();

    const int row = rt * 128 + threadIdx.x;
    const float* wp = W_ih + ((size_t)l * G4 + row) * LETTERS;

    float acc[16];
#pragma unroll
    for (int tt = 0; tt < 16; tt++) acc[tt] = 0.0f;

    for (int k = 0; k < LETTERS; k++) {
        float w = __ldg(wp + k);
#pragma unroll
        for (int tt = 0; tt < 16; tt++) acc[tt] += w * Xsm[tt * LETTERS + k];
    }

    const float bias = b_ih[l * G4 + row] + b_hh[l * G4 + row];
#pragma unroll
    for (int tt = 0; tt < 16; tt++) {
        size_t idx = (((size_t)(t0 + tt)) * LAYERS + l) * G4 + row;
        g_gin[idx] = acc[tt] + bias;
    }

    // One block resets the recurrent state + barrier (stream-ordered before phase 2)
    if (blockIdx.x == 0 && blockIdx.y == 0 && blockIdx.z == 0) {
        if (threadIdx.x == 0) g_bar = 0;
        for (int i = threadIdx.x; i < HIDDEN; i += 128) {
            g_h[0][i] = 0.0f;
            g_h[1][i] = 0.0f;
        }
    }
}

// ---------------------------------------------------------------------------
// Phase 2: persistent recurrent kernel. 128 CTAs x 256 threads.
// CTA b owns h-indices [8b, 8b+8) -> 32 rows of W_hh (4 gates x 8).
// warp w handles rows ridx = 4w..4w+3; 8 lanes per row, 128 elems each.
// ---------------------------------------------------------------------------
__global__ void __launch_bounds__(TPB, 1)
lstm_kernel(const float* __restrict__ W_hh,
            const float* __restrict__ W_lin,
            const float* __restrict__ b_lin,
            const float* __restrict__ W_out,
            const float* __restrict__ b_out,
            float* __restrict__ out) {
    __shared__ float h_sm[HIDDEN];
    __shared__ float g_sm[32];
    __shared__ float feat_sm[16];

    const int tid  = threadIdx.x;
    const int bb   = blockIdx.x;
    const int w    = tid >> 5;
    const int lane = tid & 31;
    const int rr   = lane >> 3;   // 0..3 : row within warp's group
    const int sub  = lane & 7;    // 0..7 : k-chunk
    const int ridx = w * 4 + rr;  // 0..31
    const int gate = ridx >> 3;   // 0..3
    const int jj   = ridx & 7;    // 0..7
    const int row  = gate * HIDDEN + bb * 8 + jj;

    float c = 0.0f;               // valid for tid < 8 (thread tid owns c[8*bb+tid])
    unsigned target = 0;
    int p = 0;

    for (int cell = 0; cell < NCELLS; cell++) {
        // ---- grid barrier (release h writes of previous cell, acquire all) ----
        target += NCTA;
        if (tid == 0) {
            __threadfence();
            atomicAdd(&g_bar, 1u);
            while (ld_acquire_u32(&g_bar) < target) { }
        }
        __syncthreads();

        // ---- load h into smem (256 threads x float4 = 1024 floats) ----
        ((float4*)h_sm)[tid] = ((const float4*)g_h[p])[tid];
        __syncthreads();

        const int t = cell >> 3;
        const int l = cell & 7;

        // ---- partial dot: 128 elems per thread, float4 ----
        const float4* wp = (const float4*)(W_hh + (((size_t)l * G4 + row) * HIDDEN) + sub * 128);
        const float4* hp = ((const float4*)h_sm) + sub * 32;

        float acc = (sub == 0) ? g_gin[(((size_t)t) * LAYERS + l) * G4 + row] : 0.0f;
#pragma unroll 8
        for (int it = 0; it < 32; it++) {
            float4 wv = __ldg(&wp[it]);
            float4 hv = hp[it];
            acc += wv.x * hv.x;
            acc += wv.y * hv.y;
            acc += wv.z * hv.z;
            acc += wv.w * hv.w;
        }
        // reduce across the 8 lanes of this row
        acc += __shfl_xor_sync(0xffffffffu, acc, 4);
        acc += __shfl_xor_sync(0xffffffffu, acc, 2);
        acc += __shfl_xor_sync(0xffffffffu, acc, 1);
        if (sub == 0) g_sm[ridx] = acc;
        __syncthreads();

        // ---- gates + state update (8 threads, one per owned h index) ----
        if (tid < 8) {
            float iv = sigmoidf_(g_sm[tid]);
            float fv = sigmoidf_(g_sm[8 + tid]);
            float gv = tanhf(g_sm[16 + tid]);
            float ov = sigmoidf_(g_sm[24 + tid]);
            c = fv * c + iv * gv;
            float h = ov * tanhf(c);
            g_h[p ^ 1][bb * 8 + tid] = h;
        }
        __syncthreads();   // protect g_sm before next cell; order h writes before barrier
        p ^= 1;
    }

    // ---- publish final c, final barrier, epilogue on CTA 0 ----
    if (tid < 8) g_c[bb * 8 + tid] = c;
    __syncthreads();
    target += NCTA;
    if (tid == 0) {
        __threadfence();
        atomicAdd(&g_bar, 1u);
        while (ld_acquire_u32(&g_bar) < target) { }
    }
    __syncthreads();

    if (bb == 0) {
        if (tid < 16) {
            const float* wl = W_lin + tid * HIDDEN;
            float a = b_lin[tid];
            for (int k = 0; k < HIDDEN; k++) a += wl[k] * g_c[k];
            feat_sm[tid] = a;
        }
        __syncthreads();
        if (tid == 0) {
            float s = b_out[0];
#pragma unroll
            for (int k = 0; k < 16; k++) s += W_out[k] * feat_sm[k];
            out[0] = 1.0f / (1.0f + expf(-s));
        }
    }
}

// ---------------------------------------------------------------------------
// Harness entry. Inputs (metadata order):
// 0 website, 1 payload, 2 W_ih, 3 W_hh, 4 b_ih, 5 b_hh,
// 6 W_lin, 7 b_lin, 8 W_out, 9 b_out
// ---------------------------------------------------------------------------
extern "C" void kernel_launch(void* const* d_in, const int* in_sizes, int n_in,
                              void* d_out, int out_size) {
    const float* website = (const float*)d_in[0];
    const float* payload = (const float*)d_in[1];
    const float* W_ih    = (const float*)d_in[2];
    const float* W_hh    = (const float*)d_in[3];
    const float* b_ih    = (const float*)d_in[4];
    const float* b_hh    = (const float*)d_in[5];
    const float* W_lin   = (const float*)d_in[6];
    const float* b_lin   = (const float*)d_in[7];
    const float* W_out   = (const float*)d_in[8];
    const float* b_out   = (const float*)d_in[9];
    float* out = (float*)d_out;

    dim3 grid1(32, 8, 256);
    precompute_kernel<<<grid1, 128>>>(website, payload, W_ih, b_ih, b_hh);
    lstm_kernel<<<NCTA, TPB>>>(W_hh, W_lin, b_lin, W_out, b_out, out);
}

// round 2
// speedup vs baseline: 3.4840x; 3.4840x over previous
#include <cuda_runtime.h>
#include <cuda_fp16.h>

// Problem constants
#define T_TOTAL 4096
#define LAYERS  8
#define HIDDEN  1024
#define G4      4096   // 4*HIDDEN gate rows
#define LETTERS 100
#define NCTA    128
#define TPB     256
#define NCELLS  (T_TOTAL * LAYERS)   // 32768

// ---------------------------------------------------------------------------
// Device scratch (static allocations only — no cudaMalloc allowed)
// ---------------------------------------------------------------------------
__device__ float g_gin[(size_t)T_TOTAL * LAYERS * G4];                  // 512 MB, streamed once
__device__ __half g_w2[(size_t)LAYERS * NCTA * 32 * HIDDEN];            // 64 MB fp16 repacked W_hh (L2-resident)
__device__ __align__(16) float g_h[2][HIDDEN];                          // ping-pong hidden state (fp32)
__device__ __align__(16) float g_c[HIDDEN];                             // final cell state
__device__ int g_flags[NCTA * 32];                                      // broadcast barrier flags (128B padded)

__device__ __forceinline__ int ld_acquire_s32(const int* p) {
    int v;
    asm volatile("ld.acquire.gpu.global.u32 %0, [%1];" : "=r"(v) : "l"(p) : "memory");
    return v;
}

__device__ __forceinline__ float sigmoidf_(float x) {
    return 1.0f / (1.0f + expf(-x));
}

// ---------------------------------------------------------------------------
// Phase 1a: precompute input projections  gin[cell][row] = W_ih@x_t + b_ih + b_hh
// grid (32 rtiles, 8 layers, 256 ttiles), block 128. Also resets state/flags.
// ---------------------------------------------------------------------------
__global__ void precompute_kernel(const float* __restrict__ website,
                                  const float* __restrict__ payload,
                                  const float* __restrict__ W_ih,
                                  const float* __restrict__ b_ih,
                                  const float* __restrict__ b_hh) {
    __shared__ float Xsm[16 * LETTERS];
    const int rt = blockIdx.x;
    const int l  = blockIdx.y;
    const int t0 = blockIdx.z * 16;

    for (int idx = threadIdx.x; idx < 16 * LETTERS; idx += 128) {
        int tt = idx / LETTERS, k = idx % LETTERS;
        int t = t0 + tt;
        Xsm[idx] = (t < 2048) ? website[t * LETTERS + k]
                              : payload[(t - 2048) * LETTERS + k];
    }
    __syncthreads();

    const int row = rt * 128 + threadIdx.x;
    const float* wp = W_ih + ((size_t)l * G4 + row) * LETTERS;

    float acc[16];
#pragma unroll
    for (int tt = 0; tt < 16; tt++) acc[tt] = 0.0f;

    for (int k = 0; k < LETTERS; k++) {
        float w = __ldg(wp + k);
#pragma unroll
        for (int tt = 0; tt < 16; tt++) acc[tt] += w * Xsm[tt * LETTERS + k];
    }

    const float bias = b_ih[l * G4 + row] + b_hh[l * G4 + row];
#pragma unroll
    for (int tt = 0; tt < 16; tt++) {
        size_t idx = (((size_t)(t0 + tt)) * LAYERS + l) * G4 + row;
        g_gin[idx] = acc[tt] + bias;
    }

    if (blockIdx.x == 0 && blockIdx.y == 0 && blockIdx.z == 0) {
        for (int i = threadIdx.x; i < HIDDEN; i += 128) {
            g_h[0][i] = 0.0f;
            g_h[1][i] = 0.0f;
        }
        for (int i = threadIdx.x; i < NCTA * 32; i += 128) g_flags[i] = 0;
    }
}

// ---------------------------------------------------------------------------
// Phase 1b: repack W_hh (fp32 [l][row][k]) -> fp16 g_w2 in compute layout.
// CTA bb owns h-indices 8bb..8bb+8; its 32 rows r = g*8+j map to global
// row g*1024 + bb*8 + j. Within a row, halfs are permuted so that the warp's
// uint4 load #n (lanes contiguous 16B) carries k-set:
//   q<4 : k = it*256 +      lane*4 + q
//   q>=4: k = it*256 + 128 + lane*4 + (q-4)
// which pairs with conflict-free LDS.128 reads of h.
// ---------------------------------------------------------------------------
__global__ void repack_whh_kernel(const float* __restrict__ W_hh) {
    size_t idx = (size_t)blockIdx.x * 1024 + threadIdx.x;   // over 8*4096*1024
    int k = (int)(idx & 1023);
    size_t rowl = idx >> 10;
    int row = (int)(rowl & 4095);
    int l   = (int)(rowl >> 12);
    int g = row >> 10, rem = row & 1023, bb = rem >> 3, j = rem & 7;
    int r = g * 8 + j;
    int it = k >> 8;
    int part = (k & 255) >> 7;
    int lane = (k & 127) >> 2;
    int q = part * 4 + (k & 3);
    int off = (it * 32 + lane) * 8 + q;
    g_w2[((((size_t)l * NCTA) + bb) * 32 + r) * HIDDEN + off] = __float2half(W_hh[idx]);
}

// ---------------------------------------------------------------------------
// Phase 2: persistent recurrent kernel. 128 CTAs x 256 threads.
// warp w handles rows r = 4w..4w+3 (r = gate*8 + j).
// ---------------------------------------------------------------------------
__global__ void __launch_bounds__(TPB, 1)
lstm_kernel(const float* __restrict__ W_lin,
            const float* __restrict__ b_lin,
            const float* __restrict__ W_out,
            const float* __restrict__ b_out,
            float* __restrict__ out) {
    __shared__ __align__(16) float h_sm[HIDDEN];
    __shared__ float g_sm[32];
    __shared__ float gin_sm[32];
    __shared__ float feat_sm[16];

    const int tid  = threadIdx.x;
    const int bb   = blockIdx.x;
    const int w    = tid >> 5;
    const int lane = tid & 31;

    // base of this warp's 4 weight rows (in uint4 units; row = 128 uint4)
    const uint4* __restrict__ wbase0 =
        (const uint4*)(g_w2 + (((size_t)0 * NCTA + bb) * 32 + w * 4) * HIDDEN);
    const size_t layer_stride_u4 = (size_t)NCTA * 32 * HIDDEN / 8;   // uint4 per layer

    float c = 0.0f;   // thread tid<8 owns c[8*bb+tid]
    int p = 0;

    for (int cell = 0; cell < NCELLS; cell++) {
        const int l = cell & 7;

        // ---- prefetch weights for this cell (hidden behind the barrier) ----
        const uint4* wrow = wbase0 + (size_t)l * layer_stride_u4;
        uint4 wreg[16];
#pragma unroll
        for (int r = 0; r < 4; r++)
#pragma unroll
            for (int it = 0; it < 4; it++)
                wreg[r * 4 + it] = __ldg(&wrow[(size_t)r * 128 + it * 32 + lane]);

        // ---- prefetch gin (warp 0; streaming hint to protect L2 residency) ----
        if (tid < 32) {
            int g = tid >> 3, j = tid & 7;
            gin_sm[tid] = __ldcs(&g_gin[(size_t)cell * G4 + g * HIDDEN + bb * 8 + j]);
        }

        // ---- broadcast-flag grid barrier: wait for all CTAs to finish cell-1 ----
        if (tid < NCTA) {
            const int* fp = &g_flags[tid * 32];
            while (ld_acquire_s32(fp) < cell) { }
        }
        __syncthreads();

        // ---- load h (4KB) into smem, coalesced float4 ----
        ((float4*)h_sm)[tid] = ((const float4*)g_h[p])[tid];
        __syncthreads();

        // ---- h into regs: conflict-free LDS.128 ----
        float4 hA[4], hB[4];
#pragma unroll
        for (int it = 0; it < 4; it++) {
            hA[it] = *(const float4*)&h_sm[it * 256 + lane * 4];
            hB[it] = *(const float4*)&h_sm[it * 256 + 128 + lane * 4];
        }

        // ---- 4 row dot-products per warp ----
        float acc[4] = {0.f, 0.f, 0.f, 0.f};
#pragma unroll
        for (int r = 0; r < 4; r++) {
#pragma unroll
            for (int it = 0; it < 4; it++) {
                uint4 wv = wreg[r * 4 + it];
                const __half2* hp = (const __half2*)&wv;
                float2 f0 = __half22float2(hp[0]);
                float2 f1 = __half22float2(hp[1]);
                float2 f2 = __half22float2(hp[2]);
                float2 f3 = __half22float2(hp[3]);
                acc[r] += f0.x * hA[it].x + f0.y * hA[it].y;
                acc[r] += f1.x * hA[it].z + f1.y * hA[it].w;
                acc[r] += f2.x * hB[it].x + f2.y * hB[it].y;
                acc[r] += f3.x * hB[it].z + f3.y * hB[it].w;
            }
        }

        // ---- reduce each row across the warp ----
#pragma unroll
        for (int s = 16; s > 0; s >>= 1) {
            acc[0] += __shfl_xor_sync(0xffffffffu, acc[0], s);
            acc[1] += __shfl_xor_sync(0xffffffffu, acc[1], s);
            acc[2] += __shfl_xor_sync(0xffffffffu, acc[2], s);
            acc[3] += __shfl_xor_sync(0xffffffffu, acc[3], s);
        }
        if (lane == 0) {
            g_sm[w * 4 + 0] = acc[0];
            g_sm[w * 4 + 1] = acc[1];
            g_sm[w * 4 + 2] = acc[2];
            g_sm[w * 4 + 3] = acc[3];
        }
        __syncthreads();

        // ---- gates + state update + publish h (warp 0, 8 threads) ----
        if (tid < 8) {
            float gi = g_sm[tid]      + gin_sm[tid];
            float gf = g_sm[8 + tid]  + gin_sm[8 + tid];
            float gg = g_sm[16 + tid] + gin_sm[16 + tid];
            float go = g_sm[24 + tid] + gin_sm[24 + tid];
            float iv = sigmoidf_(gi);
            float fv = sigmoidf_(gf);
            float gv = tanhf(gg);
            float ov = sigmoidf_(go);
            c = fv * c + iv * gv;
            float hn = ov * tanhf(c);
            g_h[p ^ 1][bb * 8 + tid] = hn;
        }
        if (tid < 32) {
            __syncwarp(0xffffffffu);
            if (tid == 0) {
                __threadfence();
                asm volatile("st.release.gpu.global.u32 [%0], %1;"
                             :: "l"(&g_flags[bb * 32]), "r"(cell + 1) : "memory");
            }
        }
        p ^= 1;
    }

    // ---- publish final c, final barrier round, epilogue on CTA 0 ----
    if (tid < 8) g_c[bb * 8 + tid] = c;
    __syncthreads();
    if (tid == 0) {
        __threadfence();
        asm volatile("st.release.gpu.global.u32 [%0], %1;"
                     :: "l"(&g_flags[bb * 32]), "r"(NCELLS + 1) : "memory");
    }
    if (tid < NCTA) {
        const int* fp = &g_flags[tid * 32];
        while (ld_acquire_s32(fp) < NCELLS + 1) { }
    }
    __syncthreads();

    if (bb == 0) {
        if (tid < 16) {
            const float* wl = W_lin + tid * HIDDEN;
            float a = b_lin[tid];
            for (int k = 0; k < HIDDEN; k++) a += wl[k] * g_c[k];
            feat_sm[tid] = a;
        }
        __syncthreads();
        if (tid == 0) {
            float s = b_out[0];
#pragma unroll
            for (int k = 0; k < 16; k++) s += W_out[k] * feat_sm[k];
            out[0] = 1.0f / (1.0f + expf(-s));
        }
    }
}

// ---------------------------------------------------------------------------
// Harness entry. Inputs: 0 website, 1 payload, 2 W_ih, 3 W_hh, 4 b_ih,
// 5 b_hh, 6 W_lin, 7 b_lin, 8 W_out, 9 b_out
// ---------------------------------------------------------------------------
extern "C" void kernel_launch(void* const* d_in, const int* in_sizes, int n_in,
                              void* d_out, int out_size) {
    const float* website = (const float*)d_in[0];
    const float* payload = (const float*)d_in[1];
    const float* W_ih    = (const float*)d_in[2];
    const float* W_hh    = (const float*)d_in[3];
    const float* W_lin   = (const float*)d_in[6];
    const float* b_ih    = (const float*)d_in[4];
    const float* b_hh    = (const float*)d_in[5];
    const float* b_lin   = (const float*)d_in[7];
    const float* W_out   = (const float*)d_in[8];
    const float* b_out   = (const float*)d_in[9];
    float* out = (float*)d_out;

    dim3 grid1(32, 8, 256);
    precompute_kernel<<<grid1, 128>>>(website, payload, W_ih, b_ih, b_hh);
    repack_whh_kernel<<<(LAYERS * G4 * HIDDEN) / 1024, 1024>>>(W_hh);
    lstm_kernel<<<NCTA, TPB>>>(W_lin, b_lin, W_out, b_out, out);
}